// round 1
// baseline (speedup 1.0000x reference)
#include <cuda_runtime.h>
#include <cuda_bf16.h>

#define N_S   32
#define C_CH  64
#define HWsz  12544
#define HW4   3136            // HW / 4 (float4)
#define HIDDEN 8
#define T_INV (1.0f/10.0f)
#define GAMMA (12544.0f/3.0f)

// Scratch (device globals — no allocation allowed)
__device__ float g_s[N_S * HWsz];        // s, then overwritten by spatial
__device__ float g_pooled[N_S * C_CH];   // channel sums
__device__ float g_sumexp[N_S];
__device__ float g_coefA[N_S * 2 * C_CH];
__device__ float g_coefB[N_S * 2 * C_CH];

// ---------------- init: zero the atomic accumulators ----------------
__global__ void k0_init() {
    int i = blockIdx.x * blockDim.x + threadIdx.x;
    if (i < N_S * C_CH) g_pooled[i] = 0.0f;
    if (i < N_S) g_sumexp[i] = 0.0f;
}

// ---------------- K1: read x once; produce s, pooled sums, sumexp ----------------
// grid: (13, 32), block: 256. Each thread = one float4 (4 hw positions) of one sample.
__global__ void __launch_bounds__(256) k1_reduce(
    const float* __restrict__ x,
    const float* __restrict__ conv_w,
    const float* __restrict__ conv_b)
{
    const int n   = blockIdx.y;
    const int i4  = blockIdx.x * blockDim.x + threadIdx.x;
    const bool active = (i4 < HW4);
    const int tid = threadIdx.x, warp = tid >> 5, lane = tid & 31;

    __shared__ float wsh[C_CH];
    __shared__ float cpart[C_CH][8];
    __shared__ float epart[8];

    if (tid < C_CH) wsh[tid] = conv_w[tid];
    __syncthreads();

    const float4* xp = reinterpret_cast<const float4*>(x)
                     + (size_t)n * C_CH * HW4 + i4;

    float4 s = make_float4(0.f, 0.f, 0.f, 0.f);
    #pragma unroll 4
    for (int c = 0; c < C_CH; c++) {
        float4 v = active ? xp[(size_t)c * HW4] : make_float4(0.f,0.f,0.f,0.f);
        float w = wsh[c];
        s.x = fmaf(v.x, w, s.x); s.y = fmaf(v.y, w, s.y);
        s.z = fmaf(v.z, w, s.z); s.w = fmaf(v.w, w, s.w);
        float p = (v.x + v.y) + (v.z + v.w);
        p += __shfl_down_sync(0xffffffff, p, 16);
        p += __shfl_down_sync(0xffffffff, p, 8);
        p += __shfl_down_sync(0xffffffff, p, 4);
        p += __shfl_down_sync(0xffffffff, p, 2);
        p += __shfl_down_sync(0xffffffff, p, 1);
        if (lane == 0) cpart[c][warp] = p;
    }
    __syncthreads();
    if (tid < C_CH) {
        float acc = 0.f;
        #pragma unroll
        for (int w = 0; w < 8; w++) acc += cpart[tid][w];
        atomicAdd(&g_pooled[n * C_CH + tid], acc);
    }

    const float bb = conv_b[0];
    s.x += bb; s.y += bb; s.z += bb; s.w += bb;
    if (active)
        reinterpret_cast<float4*>(g_s)[n * HW4 + i4] = s;

    float e = 0.f;
    if (active)
        e = __expf(s.x * T_INV) + __expf(s.y * T_INV)
          + __expf(s.z * T_INV) + __expf(s.w * T_INV);
    e += __shfl_down_sync(0xffffffff, e, 16);
    e += __shfl_down_sync(0xffffffff, e, 8);
    e += __shfl_down_sync(0xffffffff, e, 4);
    e += __shfl_down_sync(0xffffffff, e, 2);
    e += __shfl_down_sync(0xffffffff, e, 1);
    if (lane == 0) epart[warp] = e;
    __syncthreads();
    if (tid == 0) {
        float acc = 0.f;
        #pragma unroll
        for (int w = 0; w < 8; w++) acc += epart[w];
        atomicAdd(&g_sumexp[n], acc);
    }
}

// ---------------- K2: tiny FC chain -> per-sample coefficients ----------------
// grid: 32, block: 256 (one block per sample)
__global__ void __launch_bounds__(256) k2_coef(
    const float* __restrict__ w1, const float* __restrict__ b1,
    const float* __restrict__ w2, const float* __restrict__ b2)
{
    const int n = blockIdx.x, tid = threadIdx.x;
    __shared__ float ps[C_CH];
    __shared__ float hs[HIDDEN];

    if (tid < C_CH) ps[tid] = g_pooled[n * C_CH + tid] * (1.0f / (float)HWsz);
    __syncthreads();
    if (tid < HIDDEN) {
        float a = b1[tid];
        #pragma unroll
        for (int c = 0; c < C_CH; c++) a = fmaf(ps[c], w1[c * HIDDEN + tid], a);
        hs[tid] = fmaxf(a, 0.0f);
    }
    __syncthreads();

    float o = b2[tid];
    #pragma unroll
    for (int j = 0; j < HIDDEN; j++) o = fmaf(hs[j], w2[j * 256 + tid], o);
    float sig = 1.0f / (1.0f + __expf(-o));
    float val = 2.0f * sig - 1.0f;

    int sel = tid & 1;
    int c   = (tid >> 1) & 63;
    int k   = tid >> 7;
    float init = (k == 0) ? 1.0f : 0.0f;
    if (sel == 0) g_coefA[n * 128 + k * 64 + c] = init + 1.0f * val;
    else          g_coefB[n * 128 + k * 64 + c] = init + 0.5f * val;
}

// ---------------- K3: s -> spatial (in place) ----------------
__global__ void __launch_bounds__(256) k3_spatial() {
    int idx = blockIdx.x * blockDim.x + threadIdx.x;   // float4 index
    if (idx >= N_S * HW4) return;
    int n = idx / HW4;
    float inv = GAMMA / g_sumexp[n];
    float4 s = reinterpret_cast<float4*>(g_s)[idx];
    float4 sp;
    sp.x = fminf(__expf(s.x * T_INV) * inv, 1.0f);
    sp.y = fminf(__expf(s.y * T_INV) * inv, 1.0f);
    sp.z = fminf(__expf(s.z * T_INV) * inv, 1.0f);
    sp.w = fminf(__expf(s.w * T_INV) * inv, 1.0f);
    reinterpret_cast<float4*>(g_s)[idx] = sp;
}

// ---------------- K4: main output pass ----------------
// total float4 = 32*64*3136 = 6,422,528 ; 25088 blocks x 256 threads exactly
__global__ void __launch_bounds__(256) k4_out(
    const float* __restrict__ x, float* __restrict__ out)
{
    size_t idx = (size_t)blockIdx.x * blockDim.x + threadIdx.x;
    int i4 = (int)(idx % HW4);
    int nc = (int)(idx / HW4);
    int c  = nc & 63;
    int n  = nc >> 6;

    float a0 = __ldg(&g_coefA[n * 128 + c]);
    float a1 = __ldg(&g_coefA[n * 128 + 64 + c]);
    float b0 = __ldg(&g_coefB[n * 128 + c]);
    float b1 = __ldg(&g_coefB[n * 128 + 64 + c]);

    float4 v  = reinterpret_cast<const float4*>(x)[idx];
    float4 sp = __ldg(&reinterpret_cast<const float4*>(g_s)[n * HW4 + i4]);

    float4 o;
    o.x = sp.x * fmaxf(fmaf(v.x, a0, b0), fmaf(v.x, a1, b1));
    o.y = sp.y * fmaxf(fmaf(v.y, a0, b0), fmaf(v.y, a1, b1));
    o.z = sp.z * fmaxf(fmaf(v.z, a0, b0), fmaf(v.z, a1, b1));
    o.w = sp.w * fmaxf(fmaf(v.w, a0, b0), fmaf(v.w, a1, b1));
    reinterpret_cast<float4*>(out)[idx] = o;
}

extern "C" void kernel_launch(void* const* d_in, const int* in_sizes, int n_in,
                              void* d_out, int out_size)
{
    const float* x      = (const float*)d_in[0];
    const float* conv_w = (const float*)d_in[1];
    const float* conv_b = (const float*)d_in[2];
    const float* w1     = (const float*)d_in[3];
    const float* b1     = (const float*)d_in[4];
    const float* w2     = (const float*)d_in[5];
    const float* b2     = (const float*)d_in[6];
    float* out = (float*)d_out;

    k0_init<<<(N_S * C_CH + 255) / 256, 256>>>();
    {
        dim3 grid((HW4 + 255) / 256, N_S);
        k1_reduce<<<grid, 256>>>(x, conv_w, conv_b);
    }
    k2_coef<<<N_S, 256>>>(w1, b1, w2, b2);
    k3_spatial<<<(N_S * HW4 + 255) / 256, 256>>>();
    {
        size_t total4 = (size_t)N_S * C_CH * HW4;
        k4_out<<<(unsigned)(total4 / 256), 256>>>(x, out);
    }
}

// round 2
// speedup vs baseline: 1.2454x; 1.2454x over previous
#include <cuda_runtime.h>
#include <cuda_bf16.h>

#define N_S    32
#define C_CH   64
#define HWsz   12544
#define HW4    3136            // HW / 4 (float4)
#define HIDDEN 8
#define T_INV  (1.0f/10.0f)
#define GAMMA  (12544.0f/3.0f)
#define NB1    13              // k1 blocks per sample (13*256 >= 3136)

// Scratch (device globals — allocation is forbidden)
__device__ float4 g_s4[N_S * HW4];          // raw s (with bias), float4 per 4 hw
__device__ float  g_cpart[N_S * NB1 * C_CH]; // per-block channel partial sums
__device__ float  g_epart[N_S * NB1];        // per-block exp partial sums

// ================= K1: read x once -> s, channel partials, exp partials ======
// grid (13, 32), block 256. Warp w owns channels [8w, 8w+8).
__global__ void __launch_bounds__(256) k1_reduce(
    const float* __restrict__ x,
    const float* __restrict__ conv_w,
    const float* __restrict__ conv_b)
{
    const int n    = blockIdx.y;
    const int bx   = blockIdx.x;
    const int base = bx * 256;
    const int tid  = threadIdx.x;
    const int warp = tid >> 5, lane = tid & 31;
    const int c0   = warp * 8;

    __shared__ float4 smem_s[8][256];   // per-warp partial s over its 8 channels
    __shared__ float  wsh[C_CH];
    __shared__ float  epart[8];

    if (tid < C_CH) wsh[tid] = conv_w[tid];
    __syncthreads();

    float pool[8];
    #pragma unroll
    for (int i = 0; i < 8; i++) pool[i] = 0.f;

    const float4* xb = reinterpret_cast<const float4*>(x)
                     + ((size_t)n * C_CH + c0) * HW4 + base + lane;

    #pragma unroll
    for (int it = 0; it < 8; it++) {
        const int pos = base + it * 32 + lane;
        const bool ok = pos < HW4;
        float4 s4 = make_float4(0.f, 0.f, 0.f, 0.f);
        #pragma unroll
        for (int c8 = 0; c8 < 8; c8++) {
            float4 v = ok ? xb[(size_t)c8 * HW4 + it * 32]
                          : make_float4(0.f, 0.f, 0.f, 0.f);
            float w = wsh[c0 + c8];
            pool[c8] += (v.x + v.y) + (v.z + v.w);
            s4.x = fmaf(v.x, w, s4.x); s4.y = fmaf(v.y, w, s4.y);
            s4.z = fmaf(v.z, w, s4.z); s4.w = fmaf(v.w, w, s4.w);
        }
        smem_s[warp][it * 32 + lane] = s4;
    }

    // reduce the 8 per-channel accumulators across the warp
    #pragma unroll
    for (int c8 = 0; c8 < 8; c8++) {
        float p = pool[c8];
        p += __shfl_down_sync(0xffffffff, p, 16);
        p += __shfl_down_sync(0xffffffff, p, 8);
        p += __shfl_down_sync(0xffffffff, p, 4);
        p += __shfl_down_sync(0xffffffff, p, 2);
        p += __shfl_down_sync(0xffffffff, p, 1);
        pool[c8] = p;
    }
    if (lane == 0) {
        float* dst = &g_cpart[((size_t)n * NB1 + bx) * C_CH + c0];
        #pragma unroll
        for (int c8 = 0; c8 < 8; c8++) dst[c8] = pool[c8];
    }
    __syncthreads();

    // finalize s per position, write raw s, accumulate exp sum
    const int pos = base + tid;
    float e = 0.f;
    if (pos < HW4) {
        float4 s = smem_s[0][tid];
        #pragma unroll
        for (int w = 1; w < 8; w++) {
            float4 t = smem_s[w][tid];
            s.x += t.x; s.y += t.y; s.z += t.z; s.w += t.w;
        }
        const float bb = __ldg(conv_b);
        s.x += bb; s.y += bb; s.z += bb; s.w += bb;
        g_s4[n * HW4 + pos] = s;
        e = __expf(s.x * T_INV) + __expf(s.y * T_INV)
          + __expf(s.z * T_INV) + __expf(s.w * T_INV);
    }
    e += __shfl_down_sync(0xffffffff, e, 16);
    e += __shfl_down_sync(0xffffffff, e, 8);
    e += __shfl_down_sync(0xffffffff, e, 4);
    e += __shfl_down_sync(0xffffffff, e, 2);
    e += __shfl_down_sync(0xffffffff, e, 1);
    if (lane == 0) epart[warp] = e;
    __syncthreads();
    if (tid == 0) {
        float acc = 0.f;
        #pragma unroll
        for (int w = 0; w < 8; w++) acc += epart[w];
        g_epart[n * NB1 + bx] = acc;
    }
}

// ================= K4: fused coef-FC + spatial + output pass =================
// grid (49, 32), block 256. Block = one sample n, 64 consecutive hw4 positions,
// all 64 channels. Prologue recomputes per-sample coefs (cheap, redundant).
__global__ void __launch_bounds__(256) k4_out(
    const float* __restrict__ x,
    const float* __restrict__ w1, const float* __restrict__ b1,
    const float* __restrict__ w2, const float* __restrict__ b2,
    float* __restrict__ out)
{
    const int n  = blockIdx.y;
    const int p0 = blockIdx.x * 64;
    const int tid = threadIdx.x;

    __shared__ float ps[C_CH];
    __shared__ float hs[HIDDEN];
    __shared__ float a0s[C_CH], a1s[C_CH], b0s[C_CH], b1s[C_CH];
    __shared__ float4 sp4s[64];
    __shared__ float ssum;

    // pooled mean + sumexp reduction from partials
    if (tid < C_CH) {
        float a = 0.f;
        #pragma unroll
        for (int j = 0; j < NB1; j++)
            a += g_cpart[((size_t)n * NB1 + j) * C_CH + tid];
        ps[tid] = a * (1.0f / (float)HWsz);
    }
    if (tid == 64) {
        float a = 0.f;
        #pragma unroll
        for (int j = 0; j < NB1; j++) a += g_epart[n * NB1 + j];
        ssum = a;
    }
    __syncthreads();

    if (tid < HIDDEN) {
        float a = __ldg(&b1[tid]);
        #pragma unroll
        for (int c = 0; c < C_CH; c++)
            a = fmaf(ps[c], __ldg(&w1[c * HIDDEN + tid]), a);
        hs[tid] = fmaxf(a, 0.0f);
    }
    // spatial tile for this block's 64 positions (independent of FC)
    if (tid >= 128 && tid < 192) {
        const int t = tid - 128;
        float4 s = g_s4[n * HW4 + p0 + t];
        float inv = GAMMA / ssum;
        float4 sp;
        sp.x = fminf(__expf(s.x * T_INV) * inv, 1.0f);
        sp.y = fminf(__expf(s.y * T_INV) * inv, 1.0f);
        sp.z = fminf(__expf(s.z * T_INV) * inv, 1.0f);
        sp.w = fminf(__expf(s.w * T_INV) * inv, 1.0f);
        sp4s[t] = sp;
    }
    __syncthreads();

    {
        float o = __ldg(&b2[tid]);
        #pragma unroll
        for (int j = 0; j < HIDDEN; j++)
            o = fmaf(hs[j], __ldg(&w2[j * 256 + tid]), o);
        float val = 2.0f / (1.0f + __expf(-o)) - 1.0f;  // 2*sigmoid - 1
        int sel = tid & 1;
        int c   = (tid >> 1) & 63;
        int k   = tid >> 7;
        if (k == 0) { if (sel == 0) a0s[c] = 1.0f + val; else b0s[c] = 1.0f + 0.5f * val; }
        else        { if (sel == 0) a1s[c] = val;        else b1s[c] = 0.5f * val; }
    }
    __syncthreads();

    // main pass: 64 channels x 64 positions; thread t -> position (t&63),
    // channel (t>>6) + 4*i. Each warp stays within one channel (smem bcast).
    const int p     = tid & 63;
    const int cbase = tid >> 6;
    const float4 sp = sp4s[p];

    const float4* xp = reinterpret_cast<const float4*>(x)
                     + (size_t)n * C_CH * HW4 + p0 + p;
    float4* op = reinterpret_cast<float4*>(out)
               + (size_t)n * C_CH * HW4 + p0 + p;

    #pragma unroll
    for (int i = 0; i < 16; i++) {
        const int c = cbase + i * 4;
        const float a0 = a0s[c], a1 = a1s[c], b0 = b0s[c], b1 = b1s[c];
        float4 v = __ldcs(&xp[(size_t)c * HW4]);   // last use: evict-first
        float4 o;
        o.x = sp.x * fmaxf(fmaf(v.x, a0, b0), fmaf(v.x, a1, b1));
        o.y = sp.y * fmaxf(fmaf(v.y, a0, b0), fmaf(v.y, a1, b1));
        o.z = sp.z * fmaxf(fmaf(v.z, a0, b0), fmaf(v.z, a1, b1));
        o.w = sp.w * fmaxf(fmaf(v.w, a0, b0), fmaf(v.w, a1, b1));
        __stcs(&op[(size_t)c * HW4], o);           // streaming store
    }
}

extern "C" void kernel_launch(void* const* d_in, const int* in_sizes, int n_in,
                              void* d_out, int out_size)
{
    const float* x      = (const float*)d_in[0];
    const float* conv_w = (const float*)d_in[1];
    const float* conv_b = (const float*)d_in[2];
    const float* w1     = (const float*)d_in[3];
    const float* b1     = (const float*)d_in[4];
    const float* w2     = (const float*)d_in[5];
    const float* b2     = (const float*)d_in[6];
    float* out = (float*)d_out;

    k1_reduce<<<dim3(NB1, N_S), 256>>>(x, conv_w, conv_b);
    k4_out<<<dim3(49, N_S), 256>>>(x, w1, b1, w2, b2, out);
}